// round 8
// baseline (speedup 1.0000x reference)
#include <cuda_runtime.h>
#include <cuda_fp16.h>
#include <cstdint>
#include <cstddef>

#define D_HID 2048
#define T_LEN 4096
#define M_ROWS 8192
#define KW 8192

// ---------------- scratch (static device arrays: allocation-guard safe) ----
__device__ __align__(256) __half g_xh[(size_t)M_ROWS * D_HID];
__device__ __align__(256) __half g_w1h[(size_t)D_HID * D_HID];
__device__ __align__(256) __half g_w2h[(size_t)KW * D_HID];
__device__ __align__(256) __half g_hh[(size_t)M_ROWS * D_HID];

// ---------------- helpers ---------------------------------------------------
__device__ __forceinline__ uint32_t smem_u32(const void* p) {
    uint32_t a;
    asm("{ .reg .u64 t; cvta.to.shared.u64 t, %1; cvt.u32.u64 %0, t; }"
        : "=r"(a) : "l"(p));
    return a;
}
__device__ __forceinline__ void cp16(uint32_t dst, const void* src) {
    asm volatile("cp.async.cg.shared.global [%0], [%1], 16;" :: "r"(dst), "l"(src));
}
#define CP_COMMIT() asm volatile("cp.async.commit_group;" ::: "memory")
#define CP_WAITG2() asm volatile("cp.async.wait_group 2;" ::: "memory")

__device__ __forceinline__ void ldsm4(uint32_t r[4], uint32_t addr) {
    asm volatile("ldmatrix.sync.aligned.m8n8.x4.shared.b16 {%0,%1,%2,%3}, [%4];"
        : "=r"(r[0]), "=r"(r[1]), "=r"(r[2]), "=r"(r[3]) : "r"(addr));
}
__device__ __forceinline__ void mma_f16(float c[4], const uint32_t a[4],
                                        uint32_t b0, uint32_t b1) {
    asm volatile("mma.sync.aligned.m16n8k16.row.col.f32.f16.f16.f32 "
        "{%0,%1,%2,%3}, {%4,%5,%6,%7}, {%8,%9}, {%0,%1,%2,%3};"
        : "+f"(c[0]), "+f"(c[1]), "+f"(c[2]), "+f"(c[3])
        : "r"(a[0]), "r"(a[1]), "r"(a[2]), "r"(a[3]), "r"(b0), "r"(b1));
}
__device__ __forceinline__ float silu_f(float v) { return v / (1.0f + __expf(-v)); }

// swizzled byte offset within a [rows][32 cols f16] tile (64B rows)
__device__ __forceinline__ uint32_t sw_off(int row, int c16) {
    return (uint32_t)(row * 64 + ((c16 ^ ((row >> 1) & 3)) << 4));
}

// ---------------- round: fp32 -> fp16 ---------------------------------------
__global__ void roundh_kernel(const float* __restrict__ in, __half* __restrict__ hi,
                              int n4) {
    int i = blockIdx.x * blockDim.x + threadIdx.x;
    if (i >= n4) return;
    float4 v = ((const float4*)in)[i];
    __half2 hp0 = __halves2half2(__float2half_rn(v.x), __float2half_rn(v.y));
    __half2 hp1 = __halves2half2(__float2half_rn(v.z), __float2half_rn(v.w));
    ((__half2*)hi)[2 * i] = hp0; ((__half2*)hi)[2 * i + 1] = hp1;
}

// ---------------- main mma.sync GEMM (1-pass FP16, CTA 128x256, warp 64x64) -
// stage: A_t0[128][32]@0 (8K), A_t1@8192, B_t0[256][32]@16384 (16K),
//        B_t1@32768 (16K) -> 48 KB/stage, 4 stages = 192 KB
#define STAGE_B 49152u
#define SMEM_BYTES (4 * 49152)   // 196608; epilogue reuses this region

template<int MODE>
__global__ void __launch_bounds__(256, 1)
gemm1p_kernel(const float* __restrict__ xin, const float* __restrict__ b2,
              float* __restrict__ out) {
    extern __shared__ char smem[];
    uint32_t sb = smem_u32(smem);
    const int tid = threadIdx.x;
    const int l   = tid & 31;
    const int wid = tid >> 5;
    const int wm  = wid & 1;    // 2 M-warps (64 rows each)
    const int wn  = wid >> 1;   // 4 N-warps (64 cols each)
    const int bm = blockIdx.y * 128, bn = blockIdx.x * 256;

    const __half* Ah = (MODE == 0 ? g_xh : g_hh) + (size_t)bm * D_HID;
    const __half* Bh = (MODE == 0 ? g_w1h : g_w2h) + (size_t)bn * D_HID;

    // ---- hoisted cp.async addressing ----
    // A: row = tid>>1, two c16 chunks (tid&1)*2, (tid&1)*2+1
    const int arow = tid >> 1;
    const uint32_t soA0 = sw_off(arow, (tid & 1) * 2);
    const uint32_t soA1 = sw_off(arow, (tid & 1) * 2 + 1);
    const __half* srcA = Ah + (size_t)arow * D_HID + (tid & 1) * 16;
    // B: row = tid, all 4 c16 chunks
    const uint32_t soB0 = sw_off(tid, 0), soB1 = sw_off(tid, 1),
                   soB2 = sw_off(tid, 2), soB3 = sw_off(tid, 3);
    const __half* srcB = Bh + (size_t)tid * D_HID;

    // ---- hoisted ldmatrix offsets (tile-relative) ----
    uint32_t offA[4][2], offB[4][2];
    #pragma unroll
    for (int mt = 0; mt < 4; mt++) {
        int row = wm * 64 + mt * 16 + (l & 15);
        #pragma unroll
        for (int ks = 0; ks < 2; ks++)
            offA[mt][ks] = sw_off(row, ks * 2 + (l >> 4));
    }
    #pragma unroll
    for (int nb = 0; nb < 4; nb++) {
        int row = wn * 64 + nb * 16 + (l & 15);
        #pragma unroll
        for (int ks = 0; ks < 2; ks++)
            offB[nb][ks] = sw_off(row, ks * 2 + (l >> 4));
    }

    float acc[4][8][4];
    #pragma unroll
    for (int a = 0; a < 4; a++)
        #pragma unroll
        for (int b = 0; b < 8; b++)
            #pragma unroll
            for (int c = 0; c < 4; c++) acc[a][b][c] = 0.f;

    uint32_t sb0 = sb, sb1 = sb + STAGE_B, sb2 = sb + 2 * STAGE_B,
             sb3 = sb + 3 * STAGE_B;

    // one stage = 12 cp16 per thread (A: 4, B: 8)
    #define DO_LOAD(base) do { \
        cp16((base) + soA0,          srcA);      cp16((base) + soA1,          srcA + 8); \
        cp16((base) + 8192 + soA0,   srcA + 32); cp16((base) + 8192 + soA1,   srcA + 40); \
        cp16((base) + 16384 + soB0,  srcB);      cp16((base) + 16384 + soB1,  srcB + 8); \
        cp16((base) + 16384 + soB2,  srcB + 16); cp16((base) + 16384 + soB3,  srcB + 24); \
        cp16((base) + 32768 + soB0,  srcB + 32); cp16((base) + 32768 + soB1,  srcB + 40); \
        cp16((base) + 32768 + soB2,  srcB + 48); cp16((base) + 32768 + soB3,  srcB + 56); \
        srcA += 64; srcB += 64; \
    } while (0)

    DO_LOAD(sb0); CP_COMMIT();
    DO_LOAD(sb1); CP_COMMIT();
    DO_LOAD(sb2); CP_COMMIT();

    const int NIT = D_HID / 64;   // 32
    for (int it = 0; it < NIT; it++) {
        CP_WAITG2();
        __syncthreads();
        if (it < NIT - 3) DO_LOAD(sb3);
        CP_COMMIT();

        #pragma unroll
        for (int kt = 0; kt < 2; kt++) {
            uint32_t abase = sb0 + (uint32_t)kt * 8192u;
            uint32_t bbase = sb0 + 16384u + (uint32_t)kt * 16384u;
            #pragma unroll
            for (int ks = 0; ks < 2; ks++) {
                uint32_t bh[4][4];
                #pragma unroll
                for (int nb = 0; nb < 4; nb++)
                    ldsm4(bh[nb], bbase + offB[nb][ks]);
                #pragma unroll
                for (int mt = 0; mt < 4; mt++) {
                    uint32_t ah[4];
                    ldsm4(ah, abase + offA[mt][ks]);
                    #pragma unroll
                    for (int j = 0; j < 8; j++) {
                        mma_f16(acc[mt][j], ah,
                                bh[j >> 1][j & 1], bh[j >> 1][(j & 1) + 2]);
                    }
                }
            }
        }
        uint32_t t = sb0; sb0 = sb1; sb1 = sb2; sb2 = sb3; sb3 = t;
    }
    __syncthreads();   // pipeline smem now reusable for epilogue

    if (MODE == 0) {
        // silu + round to fp16, staged for coalesced global stores
        uint32_t* h_buf = (uint32_t*)smem;            // [128][130] u32
        #pragma unroll
        for (int mt = 0; mt < 4; mt++) {
            #pragma unroll
            for (int nt = 0; nt < 8; nt++) {
                int r0 = wm * 64 + mt * 16 + (l >> 2);
                int cu = wn * 32 + nt * 4 + (l & 3);
                #pragma unroll
                for (int half = 0; half < 2; half++) {
                    int r = r0 + half * 8;
                    float v0 = silu_f(acc[mt][nt][half * 2 + 0]);
                    float v1 = silu_f(acc[mt][nt][half * 2 + 1]);
                    __half2 hp = __halves2half2(__float2half_rn(v0),
                                                __float2half_rn(v1));
                    h_buf[r * 130 + cu] = *(uint32_t*)&hp;
                }
            }
        }
        __syncthreads();
        for (int idx = tid; idx < 128 * 128; idx += 256) {
            int r = idx >> 7, c = idx & 127;
            ((uint32_t*)(g_hh + (size_t)(bm + r) * D_HID + bn))[c] = h_buf[r * 130 + c];
        }
    } else {
        // bias + causal 4-tap dynamic conv + silu (64 channels per tile)
        float* ksm = (float*)smem;                     // [4][128][65] = 133120 B
        float* xs  = (float*)(smem + 133120);          // [131][65]    =  34060 B
        float* b2s = (float*)(smem + 133120 + 34060);  // [256]
        const int b  = bm >> 12;
        const int t0 = bm & (T_LEN - 1);
        const int d0 = bn >> 2;
        for (int idx = tid; idx < 131 * 64; idx += 256) {
            int r = idx >> 6, c = idx & 63;
            int t = t0 - 3 + r;
            float v = 0.f;
            if (t >= 0) v = xin[((size_t)b * T_LEN + t) * D_HID + d0 + c];
            xs[r * 65 + c] = v;
        }
        b2s[tid] = b2[bn + tid];
        __syncthreads();
        #pragma unroll
        for (int mt = 0; mt < 4; mt++) {
            #pragma unroll
            for (int nt = 0; nt < 8; nt++) {
                int r0   = wm * 64 + mt * 16 + (l >> 2);
                int col0 = wn * 64 + nt * 8 + (l & 3) * 2;
                #pragma unroll
                for (int cc = 0; cc < 4; cc++) {
                    int r   = r0 + ((cc >> 1) << 3);
                    int col = col0 + (cc & 1);
                    float val = acc[mt][nt][cc] + b2s[col];
                    ksm[(((col & 3) * 128) + r) * 65 + (col >> 2)] = val;
                }
            }
        }
        __syncthreads();
        {
            int c = tid & 63, rg = tid >> 6;   // rg 0..3, 32 rows each
            #pragma unroll
            for (int i = 0; i < 32; i++) {
                int r = rg * 32 + i;
                float y = 0.f;
                #pragma unroll
                for (int w = 0; w < 4; w++)
                    y += xs[(r + w) * 65 + c] * ksm[((w * 128) + r) * 65 + c];
                out[(size_t)(bm + r) * D_HID + d0 + c] = silu_f(y);
            }
        }
    }
}

// ---------------- launch ----------------------------------------------------
extern "C" void kernel_launch(void* const* d_in, const int* in_sizes, int n_in,
                              void* d_out, int out_size) {
    const float* x  = (const float*)d_in[0];   // [2,4096,2048]
    const float* w1 = (const float*)d_in[1];   // [2048,2048]
    const float* w2 = (const float*)d_in[2];   // [8192,2048]
    const float* b2 = (const float*)d_in[3];   // [8192]
    float* out = (float*)d_out;

    cudaFuncSetAttribute(gemm1p_kernel<0>, cudaFuncAttributeMaxDynamicSharedMemorySize, SMEM_BYTES);
    cudaFuncSetAttribute(gemm1p_kernel<1>, cudaFuncAttributeMaxDynamicSharedMemorySize, SMEM_BYTES);

    void *pxh, *pw1, *pw2;
    cudaGetSymbolAddress(&pxh, g_xh);
    cudaGetSymbolAddress(&pw1, g_w1h);
    cudaGetSymbolAddress(&pw2, g_w2h);

    {
        int n4 = M_ROWS * D_HID / 4;
        roundh_kernel<<<(n4 + 255) / 256, 256>>>(x, (__half*)pxh, n4);
    }
    {
        int n4 = D_HID * D_HID / 4;
        roundh_kernel<<<(n4 + 255) / 256, 256>>>(w1, (__half*)pw1, n4);
    }
    {
        int n4 = KW * D_HID / 4;
        roundh_kernel<<<(n4 + 255) / 256, 256>>>(w2, (__half*)pw2, n4);
    }

    dim3 g1(D_HID / 256, M_ROWS / 128);   // (8, 64)
    gemm1p_kernel<0><<<g1, 256, SMEM_BYTES>>>(x, b2, out);

    dim3 g2(KW / 256, M_ROWS / 128);      // (32, 64)
    gemm1p_kernel<1><<<g2, 256, SMEM_BYTES>>>(x, b2, out);
}

// round 9
// speedup vs baseline: 1.6881x; 1.6881x over previous
#include <cuda_runtime.h>
#include <cuda_fp16.h>
#include <cstdint>
#include <cstddef>

#define D_HID 2048
#define T_LEN 4096
#define M_ROWS 8192
#define KW 8192

// ---------------- scratch (static device arrays: allocation-guard safe) ----
__device__ __align__(256) __half g_xh[(size_t)M_ROWS * D_HID];
__device__ __align__(256) __half g_w1h[(size_t)D_HID * D_HID];
__device__ __align__(256) __half g_w2h[(size_t)KW * D_HID];
__device__ __align__(256) __half g_hh[(size_t)M_ROWS * D_HID];

// ---------------- helpers ---------------------------------------------------
__device__ __forceinline__ uint32_t smem_u32(const void* p) {
    uint32_t a;
    asm("{ .reg .u64 t; cvta.to.shared.u64 t, %1; cvt.u32.u64 %0, t; }"
        : "=r"(a) : "l"(p));
    return a;
}
__device__ __forceinline__ void cp16(uint32_t dst, const void* src) {
    asm volatile("cp.async.cg.shared.global [%0], [%1], 16;" :: "r"(dst), "l"(src));
}
#define CP_COMMIT() asm volatile("cp.async.commit_group;" ::: "memory")
#define CP_WAIT1()  asm volatile("cp.async.wait_group 1;" ::: "memory")

__device__ __forceinline__ void ldsm4(uint32_t r[4], uint32_t addr) {
    asm volatile("ldmatrix.sync.aligned.m8n8.x4.shared.b16 {%0,%1,%2,%3}, [%4];"
        : "=r"(r[0]), "=r"(r[1]), "=r"(r[2]), "=r"(r[3]) : "r"(addr));
}
__device__ __forceinline__ void mma_f16(float c[4], const uint32_t a[4],
                                        uint32_t b0, uint32_t b1) {
    asm volatile("mma.sync.aligned.m16n8k16.row.col.f32.f16.f16.f32 "
        "{%0,%1,%2,%3}, {%4,%5,%6,%7}, {%8,%9}, {%0,%1,%2,%3};"
        : "+f"(c[0]), "+f"(c[1]), "+f"(c[2]), "+f"(c[3])
        : "r"(a[0]), "r"(a[1]), "r"(a[2]), "r"(a[3]), "r"(b0), "r"(b1));
}
__device__ __forceinline__ float silu_f(float v) { return v / (1.0f + __expf(-v)); }

// swizzled byte offset within a [rows][32 cols f16] tile (64B rows)
__device__ __forceinline__ uint32_t sw_off(int row, int c16) {
    return (uint32_t)(row * 64 + ((c16 ^ ((row >> 1) & 3)) << 4));
}

// ---------------- round: fp32 -> fp16 ---------------------------------------
__global__ void roundh_kernel(const float* __restrict__ in, __half* __restrict__ hi,
                              int n4) {
    int i = blockIdx.x * blockDim.x + threadIdx.x;
    if (i >= n4) return;
    float4 v = ((const float4*)in)[i];
    __half2 hp0 = __halves2half2(__float2half_rn(v.x), __float2half_rn(v.y));
    __half2 hp1 = __halves2half2(__float2half_rn(v.z), __float2half_rn(v.w));
    ((__half2*)hi)[2 * i] = hp0; ((__half2*)hi)[2 * i + 1] = hp1;
}

// ---------------- main mma.sync GEMM (1-pass FP16, CTA 128x128, warp 64x32) -
// stage: A_t0[128][32] @0, A_t1 @8192, B_t0 @16384, B_t1 @24576 (32 KB/stage)
#define STAGE_B 32768u
#define SMEM_BYTES (3 * 32768)   // 98304; epilogue reuses this region

template<int MODE>
__global__ void __launch_bounds__(256, 2)
gemm1p_kernel(const float* __restrict__ xin, const float* __restrict__ b2,
              float* __restrict__ out) {
    extern __shared__ char smem[];
    uint32_t sb = smem_u32(smem);
    const int tid = threadIdx.x;
    const int l   = tid & 31;
    const int wid = tid >> 5;
    const int wm  = wid & 1;    // 2 M-warps (64 rows each)
    const int wn  = wid >> 1;   // 4 N-warps (32 cols each)
    const int bm = blockIdx.y * 128, bn = blockIdx.x * 128;

    const __half* Ah = (MODE == 0 ? g_xh : g_hh) + (size_t)bm * D_HID;
    const __half* Bh = (MODE == 0 ? g_w1h : g_w2h) + (size_t)bn * D_HID;

    // ---- hoisted cp.async addressing ----
    const int lrow = tid >> 2, lc16 = tid & 3;   // lrow 0..63
    const uint32_t so = sw_off(lrow, lc16);      // row+64 slot = +4096
    const __half* srcA = Ah + (size_t)lrow * D_HID + lc16 * 8;
    const __half* srcB = Bh + (size_t)lrow * D_HID + lc16 * 8;
    const size_t R64 = (size_t)64 * D_HID;

    // ---- hoisted ldmatrix offsets (tile-relative) ----
    uint32_t offA[4][2], offB[2][2];
    #pragma unroll
    for (int mt = 0; mt < 4; mt++) {
        int row = wm * 64 + mt * 16 + (l & 15);
        #pragma unroll
        for (int ks = 0; ks < 2; ks++)
            offA[mt][ks] = sw_off(row, ks * 2 + (l >> 4));
    }
    #pragma unroll
    for (int blk = 0; blk < 2; blk++) {
        int row = wn * 32 + blk * 16 + (l & 15);
        #pragma unroll
        for (int ks = 0; ks < 2; ks++)
            offB[blk][ks] = sw_off(row, ks * 2 + (l >> 4));
    }

    float acc[4][4][4];
    #pragma unroll
    for (int a = 0; a < 4; a++)
        #pragma unroll
        for (int b = 0; b < 4; b++)
            #pragma unroll
            for (int c = 0; c < 4; c++) acc[a][b][c] = 0.f;

    uint32_t sb0 = sb, sb1 = sb + STAGE_B, sb2 = sb + 2 * STAGE_B;

    // one stage (BK=64) = 8 cp16 per thread
    #define DO_LOAD(base) do { \
        uint32_t _t = (base) + so; \
        cp16(_t,              srcA);       cp16(_t + 4096,          srcA + R64); \
        cp16(_t + 8192,       srcA + 32);  cp16(_t + 8192 + 4096,   srcA + R64 + 32); \
        cp16(_t + 16384,      srcB);       cp16(_t + 16384 + 4096,  srcB + R64); \
        cp16(_t + 24576,      srcB + 32);  cp16(_t + 24576 + 4096,  srcB + R64 + 32); \
        srcA += 64; srcB += 64; \
    } while (0)

    DO_LOAD(sb0); CP_COMMIT();
    DO_LOAD(sb1); CP_COMMIT();

    const int NIT = D_HID / 64;   // 32
    for (int it = 0; it < NIT; it++) {
        CP_WAIT1();
        __syncthreads();
        if (it < NIT - 2) DO_LOAD(sb2);
        CP_COMMIT();

        // 4 k16 slices per stage; per slice: batch ALL ldsm into fresh locals,
        // then one unbroken 16-mma run. Full unroll -> ptxas overlaps next
        // slice's ldsm with the current mma burst.
        #pragma unroll
        for (int kt = 0; kt < 2; kt++) {
            uint32_t abase = sb0 + (uint32_t)kt * 8192u;
            uint32_t bbase = sb0 + 16384u + (uint32_t)kt * 8192u;
            #pragma unroll
            for (int ks = 0; ks < 2; ks++) {
                uint32_t b0[4], b1[4], a0[4], a1[4], a2[4], a3[4];
                ldsm4(b0, bbase + offB[0][ks]);
                ldsm4(b1, bbase + offB[1][ks]);
                ldsm4(a0, abase + offA[0][ks]);
                ldsm4(a1, abase + offA[1][ks]);
                ldsm4(a2, abase + offA[2][ks]);
                ldsm4(a3, abase + offA[3][ks]);

                mma_f16(acc[0][0], a0, b0[0], b0[2]);
                mma_f16(acc[0][1], a0, b0[1], b0[3]);
                mma_f16(acc[0][2], a0, b1[0], b1[2]);
                mma_f16(acc[0][3], a0, b1[1], b1[3]);
                mma_f16(acc[1][0], a1, b0[0], b0[2]);
                mma_f16(acc[1][1], a1, b0[1], b0[3]);
                mma_f16(acc[1][2], a1, b1[0], b1[2]);
                mma_f16(acc[1][3], a1, b1[1], b1[3]);
                mma_f16(acc[2][0], a2, b0[0], b0[2]);
                mma_f16(acc[2][1], a2, b0[1], b0[3]);
                mma_f16(acc[2][2], a2, b1[0], b1[2]);
                mma_f16(acc[2][3], a2, b1[1], b1[3]);
                mma_f16(acc[3][0], a3, b0[0], b0[2]);
                mma_f16(acc[3][1], a3, b0[1], b0[3]);
                mma_f16(acc[3][2], a3, b1[0], b1[2]);
                mma_f16(acc[3][3], a3, b1[1], b1[3]);
            }
        }
        uint32_t t = sb0; sb0 = sb1; sb1 = sb2; sb2 = t;
    }
    __syncthreads();   // pipeline smem now reusable for epilogue

    if (MODE == 0) {
        // silu + round to fp16, staged for coalesced global stores
        uint32_t* h_buf = (uint32_t*)smem;            // [128][66]
        #pragma unroll
        for (int mt = 0; mt < 4; mt++) {
            #pragma unroll
            for (int nt = 0; nt < 4; nt++) {
                int r0 = wm * 64 + mt * 16 + (l >> 2);
                int cu = wn * 16 + nt * 4 + (l & 3);
                #pragma unroll
                for (int half = 0; half < 2; half++) {
                    int r = r0 + half * 8;
                    float v0 = silu_f(acc[mt][nt][half * 2 + 0]);
                    float v1 = silu_f(acc[mt][nt][half * 2 + 1]);
                    __half2 hp = __halves2half2(__float2half_rn(v0),
                                                __float2half_rn(v1));
                    h_buf[r * 66 + cu] = *(uint32_t*)&hp;
                }
            }
        }
        __syncthreads();
        for (int idx = tid; idx < 128 * 64; idx += 256) {
            int r = idx >> 6, c = idx & 63;
            ((uint32_t*)(g_hh + (size_t)(bm + r) * D_HID + bn))[c] = h_buf[r * 66 + c];
        }
    } else {
        // bias + causal 4-tap dynamic conv + silu (32 channels per tile)
        float* ksm = (float*)smem;                  // [4][128][33] = 67584 B
        float* xs  = (float*)(smem + 67584);        // [131][33]    = 17292 B
        float* b2s = (float*)(smem + 67584 + 17292 + 4);  // [128]
        const int b  = bm >> 12;
        const int t0 = bm & (T_LEN - 1);
        const int d0 = bn >> 2;
        for (int idx = tid; idx < 131 * 32; idx += 256) {
            int r = idx >> 5, c = idx & 31;
            int t = t0 - 3 + r;
            float v = 0.f;
            if (t >= 0) v = xin[((size_t)b * T_LEN + t) * D_HID + d0 + c];
            xs[r * 33 + c] = v;
        }
        if (tid < 128) b2s[tid] = b2[bn + tid];
        __syncthreads();
        #pragma unroll
        for (int mt = 0; mt < 4; mt++) {
            #pragma unroll
            for (int nt = 0; nt < 4; nt++) {
                int r0   = wm * 64 + mt * 16 + (l >> 2);
                int col0 = wn * 32 + nt * 8 + (l & 3) * 2;
                #pragma unroll
                for (int cc = 0; cc < 4; cc++) {
                    int r   = r0 + ((cc >> 1) << 3);
                    int col = col0 + (cc & 1);
                    float val = acc[mt][nt][cc] + b2s[col];
                    ksm[(((col & 3) * 128) + r) * 33 + (col >> 2)] = val;
                }
            }
        }
        __syncthreads();
        {
            int c = tid & 31, rg = tid >> 5;
            #pragma unroll
            for (int i = 0; i < 16; i++) {
                int r = rg * 16 + i;
                float y = 0.f;
                #pragma unroll
                for (int w = 0; w < 4; w++)
                    y += xs[(r + w) * 33 + c] * ksm[((w * 128) + r) * 33 + c];
                out[(size_t)(bm + r) * D_HID + d0 + c] = silu_f(y);
            }
        }
    }
}

// ---------------- launch ----------------------------------------------------
extern "C" void kernel_launch(void* const* d_in, const int* in_sizes, int n_in,
                              void* d_out, int out_size) {
    const float* x  = (const float*)d_in[0];   // [2,4096,2048]
    const float* w1 = (const float*)d_in[1];   // [2048,2048]
    const float* w2 = (const float*)d_in[2];   // [8192,2048]
    const float* b2 = (const float*)d_in[3];   // [8192]
    float* out = (float*)d_out;

    cudaFuncSetAttribute(gemm1p_kernel<0>, cudaFuncAttributeMaxDynamicSharedMemorySize, SMEM_BYTES);
    cudaFuncSetAttribute(gemm1p_kernel<1>, cudaFuncAttributeMaxDynamicSharedMemorySize, SMEM_BYTES);

    void *pxh, *pw1, *pw2;
    cudaGetSymbolAddress(&pxh, g_xh);
    cudaGetSymbolAddress(&pw1, g_w1h);
    cudaGetSymbolAddress(&pw2, g_w2h);

    {
        int n4 = M_ROWS * D_HID / 4;
        roundh_kernel<<<(n4 + 255) / 256, 256>>>(x, (__half*)pxh, n4);
    }
    {
        int n4 = D_HID * D_HID / 4;
        roundh_kernel<<<(n4 + 255) / 256, 256>>>(w1, (__half*)pw1, n4);
    }
    {
        int n4 = KW * D_HID / 4;
        roundh_kernel<<<(n4 + 255) / 256, 256>>>(w2, (__half*)pw2, n4);
    }

    dim3 g1(D_HID / 128, M_ROWS / 128);   // (16, 64)
    gemm1p_kernel<0><<<g1, 256, SMEM_BYTES>>>(x, b2, out);

    dim3 g2(KW / 128, M_ROWS / 128);      // (64, 64)
    gemm1p_kernel<1><<<g2, 256, SMEM_BYTES>>>(x, b2, out);
}

// round 10
// speedup vs baseline: 1.8631x; 1.1036x over previous
#include <cuda_runtime.h>
#include <cuda_fp16.h>
#include <cstdint>
#include <cstddef>

#define D_HID 2048
#define T_LEN 4096
#define M_ROWS 8192
#define KW 8192

// ---------------- scratch (static device arrays: allocation-guard safe) ----
__device__ __align__(256) __half g_xh[(size_t)M_ROWS * D_HID];
__device__ __align__(256) __half g_w1h[(size_t)D_HID * D_HID];
__device__ __align__(256) __half g_w2h[(size_t)KW * D_HID];
__device__ __align__(256) __half g_hh[(size_t)M_ROWS * D_HID];

// ---------------- helpers ---------------------------------------------------
__device__ __forceinline__ uint32_t smem_u32(const void* p) {
    uint32_t a;
    asm("{ .reg .u64 t; cvta.to.shared.u64 t, %1; cvt.u32.u64 %0, t; }"
        : "=r"(a) : "l"(p));
    return a;
}
__device__ __forceinline__ void cp16(uint32_t dst, const void* src) {
    asm volatile("cp.async.cg.shared.global [%0], [%1], 16;" :: "r"(dst), "l"(src));
}
#define CP_COMMIT() asm volatile("cp.async.commit_group;" ::: "memory")
#define CP_WAIT1()  asm volatile("cp.async.wait_group 1;" ::: "memory")

__device__ __forceinline__ void ldsm4(uint32_t r[4], uint32_t addr) {
    asm volatile("ldmatrix.sync.aligned.m8n8.x4.shared.b16 {%0,%1,%2,%3}, [%4];"
        : "=r"(r[0]), "=r"(r[1]), "=r"(r[2]), "=r"(r[3]) : "r"(addr));
}
__device__ __forceinline__ void mma_f16(float c[4], const uint32_t a[4],
                                        uint32_t b0, uint32_t b1) {
    asm volatile("mma.sync.aligned.m16n8k16.row.col.f32.f16.f16.f32 "
        "{%0,%1,%2,%3}, {%4,%5,%6,%7}, {%8,%9}, {%0,%1,%2,%3};"
        : "+f"(c[0]), "+f"(c[1]), "+f"(c[2]), "+f"(c[3])
        : "r"(a[0]), "r"(a[1]), "r"(a[2]), "r"(a[3]), "r"(b0), "r"(b1));
}
__device__ __forceinline__ float silu_f(float v) { return v / (1.0f + __expf(-v)); }

// swizzled byte offset within a [rows][32 cols f16] tile (64B rows)
__device__ __forceinline__ uint32_t sw_off(int row, int c16) {
    return (uint32_t)(row * 64 + ((c16 ^ ((row >> 1) & 3)) << 4));
}

// ---------------- fused round: fp32 -> fp16 for x, w1, w2 (one launch) ------
#define NX4  (M_ROWS * D_HID / 4)
#define NW14 (D_HID * D_HID / 4)
#define NW24 (KW * D_HID / 4)

__global__ void round3_kernel(const float* __restrict__ x,
                              const float* __restrict__ w1,
                              const float* __restrict__ w2,
                              __half* __restrict__ xh,
                              __half* __restrict__ w1h,
                              __half* __restrict__ w2h) {
    int i = blockIdx.x * blockDim.x + threadIdx.x;
    const float* src; __half* dst; int j;
    if (i < NX4)              { src = x;  dst = xh;  j = i; }
    else if (i < NX4 + NW14)  { src = w1; dst = w1h; j = i - NX4; }
    else if (i < NX4 + NW14 + NW24) { src = w2; dst = w2h; j = i - NX4 - NW14; }
    else return;
    float4 v = ((const float4*)src)[j];
    __half2 hp0 = __halves2half2(__float2half_rn(v.x), __float2half_rn(v.y));
    __half2 hp1 = __halves2half2(__float2half_rn(v.z), __float2half_rn(v.w));
    ((__half2*)dst)[2 * j] = hp0; ((__half2*)dst)[2 * j + 1] = hp1;
}

// ---------------- main mma.sync GEMM (1-pass FP16, CTA 128x128, warp 64x32) -
// stage: A_t0[128][32] @0, A_t1 @8192, B_t0 @16384, B_t1 @24576 (32 KB/stage)
#define STAGE_B 32768u
#define SMEM_BYTES (3 * 32768)   // 98304; epilogue reuses this region

template<int MODE>
__global__ void __launch_bounds__(256, 2)
gemm1p_kernel(const float* __restrict__ xin, const float* __restrict__ b2,
              float* __restrict__ out) {
    extern __shared__ char smem[];
    uint32_t sb = smem_u32(smem);
    const int tid = threadIdx.x;
    const int l   = tid & 31;
    const int wid = tid >> 5;
    const int wm  = wid & 1;    // 2 M-warps (64 rows each)
    const int wn  = wid >> 1;   // 4 N-warps (32 cols each)
    const int bm = blockIdx.y * 128, bn = blockIdx.x * 128;

    const __half* Ah = (MODE == 0 ? g_xh : g_hh) + (size_t)bm * D_HID;
    const __half* Bh = (MODE == 0 ? g_w1h : g_w2h) + (size_t)bn * D_HID;

    // ---- hoisted cp.async addressing ----
    const int lrow = tid >> 2, lc16 = tid & 3;   // lrow 0..63
    const uint32_t so = sw_off(lrow, lc16);      // row+64 slot = +4096
    const __half* srcA = Ah + (size_t)lrow * D_HID + lc16 * 8;
    const __half* srcB = Bh + (size_t)lrow * D_HID + lc16 * 8;
    const size_t R64 = (size_t)64 * D_HID;

    // ---- hoisted ldmatrix offsets (tile-relative) ----
    uint32_t offA[4][2], offB[2][2];
    #pragma unroll
    for (int mt = 0; mt < 4; mt++) {
        int row = wm * 64 + mt * 16 + (l & 15);
        #pragma unroll
        for (int ks = 0; ks < 2; ks++)
            offA[mt][ks] = sw_off(row, ks * 2 + (l >> 4));
    }
    #pragma unroll
    for (int blk = 0; blk < 2; blk++) {
        int row = wn * 32 + blk * 16 + (l & 15);
        #pragma unroll
        for (int ks = 0; ks < 2; ks++)
            offB[blk][ks] = sw_off(row, ks * 2 + (l >> 4));
    }

    float acc[4][4][4];
    #pragma unroll
    for (int a = 0; a < 4; a++)
        #pragma unroll
        for (int b = 0; b < 4; b++)
            #pragma unroll
            for (int c = 0; c < 4; c++) acc[a][b][c] = 0.f;

    uint32_t sb0 = sb, sb1 = sb + STAGE_B, sb2 = sb + 2 * STAGE_B;

    // A-half of a stage load (4 cp16) and B-half (4 cp16)
    #define DO_LOAD_A(base) do { \
        uint32_t _t = (base) + so; \
        cp16(_t,              srcA);       cp16(_t + 4096,          srcA + R64); \
        cp16(_t + 8192,       srcA + 32);  cp16(_t + 8192 + 4096,   srcA + R64 + 32); \
        srcA += 64; \
    } while (0)
    #define DO_LOAD_B(base) do { \
        uint32_t _t = (base) + so; \
        cp16(_t + 16384,      srcB);       cp16(_t + 16384 + 4096,  srcB + R64); \
        cp16(_t + 24576,      srcB + 32);  cp16(_t + 24576 + 4096,  srcB + R64 + 32); \
        srcB += 64; \
    } while (0)

    // per-k16-slice compute: batch all ldsm, then one unbroken 16-mma run
    #define DO_SLICE(abase, bbase, ks) do { \
        uint32_t b0[4], b1[4], a0[4], a1[4], a2[4], a3[4]; \
        ldsm4(b0, (bbase) + offB[0][ks]); \
        ldsm4(b1, (bbase) + offB[1][ks]); \
        ldsm4(a0, (abase) + offA[0][ks]); \
        ldsm4(a1, (abase) + offA[1][ks]); \
        ldsm4(a2, (abase) + offA[2][ks]); \
        ldsm4(a3, (abase) + offA[3][ks]); \
        mma_f16(acc[0][0], a0, b0[0], b0[2]); \
        mma_f16(acc[0][1], a0, b0[1], b0[3]); \
        mma_f16(acc[0][2], a0, b1[0], b1[2]); \
        mma_f16(acc[0][3], a0, b1[1], b1[3]); \
        mma_f16(acc[1][0], a1, b0[0], b0[2]); \
        mma_f16(acc[1][1], a1, b0[1], b0[3]); \
        mma_f16(acc[1][2], a1, b1[0], b1[2]); \
        mma_f16(acc[1][3], a1, b1[1], b1[3]); \
        mma_f16(acc[2][0], a2, b0[0], b0[2]); \
        mma_f16(acc[2][1], a2, b0[1], b0[3]); \
        mma_f16(acc[2][2], a2, b1[0], b1[2]); \
        mma_f16(acc[2][3], a2, b1[1], b1[3]); \
        mma_f16(acc[3][0], a3, b0[0], b0[2]); \
        mma_f16(acc[3][1], a3, b0[1], b0[3]); \
        mma_f16(acc[3][2], a3, b1[0], b1[2]); \
        mma_f16(acc[3][3], a3, b1[1], b1[3]); \
    } while (0)

    DO_LOAD_A(sb0); DO_LOAD_B(sb0); CP_COMMIT();
    DO_LOAD_A(sb1); DO_LOAD_B(sb1); CP_COMMIT();

    const int NIT = D_HID / 64;   // 32
    for (int it = 0; it < NIT; it++) {
        CP_WAIT1();
        __syncthreads();
        const bool pf = (it < NIT - 2);
        if (pf) DO_LOAD_A(sb2);        // spread the LSU burst: A-half now...
        DO_SLICE(sb0, sb0 + 16384u, 0);
        DO_SLICE(sb0, sb0 + 16384u, 1);
        if (pf) DO_LOAD_B(sb2);        // ...B-half between the two kt groups
        CP_COMMIT();
        DO_SLICE(sb0 + 8192u, sb0 + 24576u, 0);
        DO_SLICE(sb0 + 8192u, sb0 + 24576u, 1);
        uint32_t t = sb0; sb0 = sb1; sb1 = sb2; sb2 = t;
    }
    __syncthreads();   // pipeline smem now reusable for epilogue

    if (MODE == 0) {
        // silu + round to fp16, staged for coalesced global stores
        uint32_t* h_buf = (uint32_t*)smem;            // [128][66]
        #pragma unroll
        for (int mt = 0; mt < 4; mt++) {
            #pragma unroll
            for (int nt = 0; nt < 4; nt++) {
                int r0 = wm * 64 + mt * 16 + (l >> 2);
                int cu = wn * 16 + nt * 4 + (l & 3);
                #pragma unroll
                for (int half = 0; half < 2; half++) {
                    int r = r0 + half * 8;
                    float v0 = silu_f(acc[mt][nt][half * 2 + 0]);
                    float v1 = silu_f(acc[mt][nt][half * 2 + 1]);
                    __half2 hp = __halves2half2(__float2half_rn(v0),
                                                __float2half_rn(v1));
                    h_buf[r * 66 + cu] = *(uint32_t*)&hp;
                }
            }
        }
        __syncthreads();
        for (int idx = tid; idx < 128 * 64; idx += 256) {
            int r = idx >> 6, c = idx & 63;
            ((uint32_t*)(g_hh + (size_t)(bm + r) * D_HID + bn))[c] = h_buf[r * 66 + c];
        }
    } else {
        // bias + causal 4-tap dynamic conv + silu (32 channels per tile)
        float* ksm = (float*)smem;                  // [4][128][33] = 67584 B
        float* xs  = (float*)(smem + 67584);        // [131][33]    = 17292 B
        float* b2s = (float*)(smem + 67584 + 17292 + 4);  // [128]
        const int b  = bm >> 12;
        const int t0 = bm & (T_LEN - 1);
        const int d0 = bn >> 2;
        for (int idx = tid; idx < 131 * 32; idx += 256) {
            int r = idx >> 5, c = idx & 31;
            int t = t0 - 3 + r;
            float v = 0.f;
            if (t >= 0) v = xin[((size_t)b * T_LEN + t) * D_HID + d0 + c];
            xs[r * 33 + c] = v;
        }
        if (tid < 128) b2s[tid] = b2[bn + tid];
        __syncthreads();
        #pragma unroll
        for (int mt = 0; mt < 4; mt++) {
            #pragma unroll
            for (int nt = 0; nt < 4; nt++) {
                int r0   = wm * 64 + mt * 16 + (l >> 2);
                int col0 = wn * 32 + nt * 8 + (l & 3) * 2;
                #pragma unroll
                for (int cc = 0; cc < 4; cc++) {
                    int r   = r0 + ((cc >> 1) << 3);
                    int col = col0 + (cc & 1);
                    float val = acc[mt][nt][cc] + b2s[col];
                    ksm[(((col & 3) * 128) + r) * 33 + (col >> 2)] = val;
                }
            }
        }
        __syncthreads();
        {
            int c = tid & 31, rg = tid >> 5;
            #pragma unroll
            for (int i = 0; i < 16; i++) {
                int r = rg * 16 + i;
                float y = 0.f;
                #pragma unroll
                for (int w = 0; w < 4; w++)
                    y += xs[(r + w) * 33 + c] * ksm[((w * 128) + r) * 33 + c];
                out[(size_t)(bm + r) * D_HID + d0 + c] = silu_f(y);
            }
        }
    }
}

// ---------------- launch ----------------------------------------------------
extern "C" void kernel_launch(void* const* d_in, const int* in_sizes, int n_in,
                              void* d_out, int out_size) {
    const float* x  = (const float*)d_in[0];   // [2,4096,2048]
    const float* w1 = (const float*)d_in[1];   // [2048,2048]
    const float* w2 = (const float*)d_in[2];   // [8192,2048]
    const float* b2 = (const float*)d_in[3];   // [8192]
    float* out = (float*)d_out;

    cudaFuncSetAttribute(gemm1p_kernel<0>, cudaFuncAttributeMaxDynamicSharedMemorySize, SMEM_BYTES);
    cudaFuncSetAttribute(gemm1p_kernel<1>, cudaFuncAttributeMaxDynamicSharedMemorySize, SMEM_BYTES);

    void *pxh, *pw1, *pw2;
    cudaGetSymbolAddress(&pxh, g_xh);
    cudaGetSymbolAddress(&pw1, g_w1h);
    cudaGetSymbolAddress(&pw2, g_w2h);

    {
        int ntot = NX4 + NW14 + NW24;
        round3_kernel<<<(ntot + 255) / 256, 256>>>(
            x, w1, w2, (__half*)pxh, (__half*)pw1, (__half*)pw2);
    }

    dim3 g1(D_HID / 128, M_ROWS / 128);   // (16, 64)
    gemm1p_kernel<0><<<g1, 256, SMEM_BYTES>>>(x, b2, out);

    dim3 g2(KW / 128, M_ROWS / 128);      // (64, 64)
    gemm1p_kernel<1><<<g2, 256, SMEM_BYTES>>>(x, b2, out);
}

// round 11
// speedup vs baseline: 1.9233x; 1.0323x over previous
#include <cuda_runtime.h>
#include <cuda_fp16.h>
#include <cstdint>
#include <cstddef>

#define D_HID 2048
#define T_LEN 4096
#define M_ROWS 8192
#define KW 8192

// ---------------- scratch (static device arrays: allocation-guard safe) ----
__device__ __align__(256) __half g_xh[(size_t)M_ROWS * D_HID];
__device__ __align__(256) __half g_w1h[(size_t)D_HID * D_HID];
__device__ __align__(256) __half g_w2h[(size_t)KW * D_HID];
__device__ __align__(256) __half g_hh[(size_t)M_ROWS * D_HID];

// ---------------- helpers ---------------------------------------------------
__device__ __forceinline__ uint32_t smem_u32(const void* p) {
    uint32_t a;
    asm("{ .reg .u64 t; cvta.to.shared.u64 t, %1; cvt.u32.u64 %0, t; }"
        : "=r"(a) : "l"(p));
    return a;
}
__device__ __forceinline__ void cp16(uint32_t dst, const void* src) {
    asm volatile("cp.async.cg.shared.global [%0], [%1], 16;" :: "r"(dst), "l"(src));
}
#define CP_COMMIT() asm volatile("cp.async.commit_group;" ::: "memory")
#define CP_WAIT1()  asm volatile("cp.async.wait_group 1;" ::: "memory")

__device__ __forceinline__ void ldsm4(uint32_t r[4], uint32_t addr) {
    asm volatile("ldmatrix.sync.aligned.m8n8.x4.shared.b16 {%0,%1,%2,%3}, [%4];"
        : "=r"(r[0]), "=r"(r[1]), "=r"(r[2]), "=r"(r[3]) : "r"(addr));
}
__device__ __forceinline__ void mma_f16(float c[4], const uint32_t a[4],
                                        uint32_t b0, uint32_t b1) {
    asm volatile("mma.sync.aligned.m16n8k16.row.col.f32.f16.f16.f32 "
        "{%0,%1,%2,%3}, {%4,%5,%6,%7}, {%8,%9}, {%0,%1,%2,%3};"
        : "+f"(c[0]), "+f"(c[1]), "+f"(c[2]), "+f"(c[3])
        : "r"(a[0]), "r"(a[1]), "r"(a[2]), "r"(a[3]), "r"(b0), "r"(b1));
}
__device__ __forceinline__ float silu_f(float v) { return v / (1.0f + __expf(-v)); }

// swizzled byte offset within a [rows][32 cols f16] tile (64B rows)
__device__ __forceinline__ uint32_t sw_off(int row, int c16) {
    return (uint32_t)(row * 64 + ((c16 ^ ((row >> 1) & 3)) << 4));
}

// ---------------- fused round: fp32 -> fp16 for x, w1, w2 (one launch) ------
#define NX4  (M_ROWS * D_HID / 4)
#define NW14 (D_HID * D_HID / 4)
#define NW24 (KW * D_HID / 4)

__global__ void round3_kernel(const float* __restrict__ x,
                              const float* __restrict__ w1,
                              const float* __restrict__ w2,
                              __half* __restrict__ xh,
                              __half* __restrict__ w1h,
                              __half* __restrict__ w2h) {
    int i = blockIdx.x * blockDim.x + threadIdx.x;
    const float* src; __half* dst; int j;
    if (i < NX4)              { src = x;  dst = xh;  j = i; }
    else if (i < NX4 + NW14)  { src = w1; dst = w1h; j = i - NX4; }
    else if (i < NX4 + NW14 + NW24) { src = w2; dst = w2h; j = i - NX4 - NW14; }
    else return;
    float4 v = ((const float4*)src)[j];
    __half2 hp0 = __halves2half2(__float2half_rn(v.x), __float2half_rn(v.y));
    __half2 hp1 = __halves2half2(__float2half_rn(v.z), __float2half_rn(v.w));
    ((__half2*)dst)[2 * j] = hp0; ((__half2*)dst)[2 * j + 1] = hp1;
}

// ---------------- main mma.sync GEMM (1-pass FP16, CTA 128x128, warp 64x32) -
// stage: A_t0[128][32] @0, A_t1 @8192, B_t0 @16384, B_t1 @24576 (32 KB/stage)
#define STAGE_B 32768u
#define SMEM_BYTES (3 * 32768)   // 98304; epilogue reuses this region

template<int MODE>
__global__ void __launch_bounds__(256, 2)
gemm1p_kernel(const float* __restrict__ xin, const float* __restrict__ b2,
              float* __restrict__ out) {
    extern __shared__ char smem[];
    uint32_t sb = smem_u32(smem);
    const int tid = threadIdx.x;
    const int l   = tid & 31;
    const int wid = tid >> 5;
    const int wm  = wid & 1;    // 2 M-warps (64 rows each)
    const int wn  = wid >> 1;   // 4 N-warps (32 cols each)
    const int bm = blockIdx.y * 128, bn = blockIdx.x * 128;

    const __half* Ah = (MODE == 0 ? g_xh : g_hh) + (size_t)bm * D_HID;
    const __half* Bh = (MODE == 0 ? g_w1h : g_w2h) + (size_t)bn * D_HID;

    // ---- hoisted cp.async addressing ----
    const int lrow = tid >> 2, lc16 = tid & 3;   // lrow 0..63
    const uint32_t so = sw_off(lrow, lc16);      // row+64 slot = +4096
    const __half* srcA = Ah + (size_t)lrow * D_HID + lc16 * 8;
    const __half* srcB = Bh + (size_t)lrow * D_HID + lc16 * 8;
    const size_t R64 = (size_t)64 * D_HID;

    // ---- hoisted ldmatrix offsets (tile-relative) ----
    uint32_t offA[4][2], offB[2][2];
    #pragma unroll
    for (int mt = 0; mt < 4; mt++) {
        int row = wm * 64 + mt * 16 + (l & 15);
        #pragma unroll
        for (int ks = 0; ks < 2; ks++)
            offA[mt][ks] = sw_off(row, ks * 2 + (l >> 4));
    }
    #pragma unroll
    for (int blk = 0; blk < 2; blk++) {
        int row = wn * 32 + blk * 16 + (l & 15);
        #pragma unroll
        for (int ks = 0; ks < 2; ks++)
            offB[blk][ks] = sw_off(row, ks * 2 + (l >> 4));
    }

    float acc[4][4][4];
    #pragma unroll
    for (int a = 0; a < 4; a++)
        #pragma unroll
        for (int b = 0; b < 4; b++)
            #pragma unroll
            for (int c = 0; c < 4; c++) acc[a][b][c] = 0.f;

    uint32_t sb0 = sb, sb1 = sb + STAGE_B, sb2 = sb + 2 * STAGE_B;

    // prefetch quarters: 2 cp16 each
    #define LD_Q0(base) do { uint32_t _t = (base) + so; \
        cp16(_t,             srcA);       cp16(_t + 4096,          srcA + R64); } while (0)
    #define LD_Q1(base) do { uint32_t _t = (base) + so; \
        cp16(_t + 8192,      srcA + 32);  cp16(_t + 8192 + 4096,   srcA + R64 + 32); \
        srcA += 64; } while (0)
    #define LD_Q2(base) do { uint32_t _t = (base) + so; \
        cp16(_t + 16384,     srcB);       cp16(_t + 16384 + 4096,  srcB + R64); } while (0)
    #define LD_Q3(base) do { uint32_t _t = (base) + so; \
        cp16(_t + 24576,     srcB + 32);  cp16(_t + 24576 + 4096,  srcB + R64 + 32); \
        srcB += 64; } while (0)

    // per-k16-slice compute: B ldsm + first A ldsm, start mma on a0 while
    // a1-a3 ldsm are in flight, then the rest as one unbroken run
    #define DO_SLICE(abase, bbase, ks) do { \
        uint32_t b0[4], b1[4], a0[4], a1[4], a2[4], a3[4]; \
        ldsm4(b0, (bbase) + offB[0][ks]); \
        ldsm4(b1, (bbase) + offB[1][ks]); \
        ldsm4(a0, (abase) + offA[0][ks]); \
        mma_f16(acc[0][0], a0, b0[0], b0[2]); \
        ldsm4(a1, (abase) + offA[1][ks]); \
        mma_f16(acc[0][1], a0, b0[1], b0[3]); \
        ldsm4(a2, (abase) + offA[2][ks]); \
        mma_f16(acc[0][2], a0, b1[0], b1[2]); \
        ldsm4(a3, (abase) + offA[3][ks]); \
        mma_f16(acc[0][3], a0, b1[1], b1[3]); \
        mma_f16(acc[1][0], a1, b0[0], b0[2]); \
        mma_f16(acc[1][1], a1, b0[1], b0[3]); \
        mma_f16(acc[1][2], a1, b1[0], b1[2]); \
        mma_f16(acc[1][3], a1, b1[1], b1[3]); \
        mma_f16(acc[2][0], a2, b0[0], b0[2]); \
        mma_f16(acc[2][1], a2, b0[1], b0[3]); \
        mma_f16(acc[2][2], a2, b1[0], b1[2]); \
        mma_f16(acc[2][3], a2, b1[1], b1[3]); \
        mma_f16(acc[3][0], a3, b0[0], b0[2]); \
        mma_f16(acc[3][1], a3, b0[1], b0[3]); \
        mma_f16(acc[3][2], a3, b1[0], b1[2]); \
        mma_f16(acc[3][3], a3, b1[1], b1[3]); \
    } while (0)

    LD_Q0(sb0); LD_Q1(sb0); LD_Q2(sb0); LD_Q3(sb0); CP_COMMIT();
    LD_Q0(sb1); LD_Q1(sb1); LD_Q2(sb1); LD_Q3(sb1); CP_COMMIT();

    const int NIT = D_HID / 64;   // 32
    for (int it = 0; it < NIT; it++) {
        CP_WAIT1();
        __syncthreads();
        const bool pf = (it < NIT - 2);
        // quarter-split prefetch: each 2-op LSU burst hides inside a 16-mma run
        if (pf) LD_Q0(sb2);
        DO_SLICE(sb0, sb0 + 16384u, 0);
        if (pf) LD_Q1(sb2);
        DO_SLICE(sb0, sb0 + 16384u, 1);
        if (pf) LD_Q2(sb2);
        DO_SLICE(sb0 + 8192u, sb0 + 24576u, 0);
        if (pf) LD_Q3(sb2);
        CP_COMMIT();
        DO_SLICE(sb0 + 8192u, sb0 + 24576u, 1);
        uint32_t t = sb0; sb0 = sb1; sb1 = sb2; sb2 = t;
    }
    __syncthreads();   // pipeline smem now reusable for epilogue

    if (MODE == 0) {
        // silu + round to fp16, staged for coalesced global stores
        uint32_t* h_buf = (uint32_t*)smem;            // [128][66]
        #pragma unroll
        for (int mt = 0; mt < 4; mt++) {
            #pragma unroll
            for (int nt = 0; nt < 4; nt++) {
                int r0 = wm * 64 + mt * 16 + (l >> 2);
                int cu = wn * 16 + nt * 4 + (l & 3);
                #pragma unroll
                for (int half = 0; half < 2; half++) {
                    int r = r0 + half * 8;
                    float v0 = silu_f(acc[mt][nt][half * 2 + 0]);
                    float v1 = silu_f(acc[mt][nt][half * 2 + 1]);
                    __half2 hp = __halves2half2(__float2half_rn(v0),
                                                __float2half_rn(v1));
                    h_buf[r * 66 + cu] = *(uint32_t*)&hp;
                }
            }
        }
        __syncthreads();
        for (int idx = tid; idx < 128 * 64; idx += 256) {
            int r = idx >> 6, c = idx & 63;
            ((uint32_t*)(g_hh + (size_t)(bm + r) * D_HID + bn))[c] = h_buf[r * 66 + c];
        }
    } else {
        // bias + causal 4-tap dynamic conv + silu (32 channels per tile)
        float* ksm = (float*)smem;                  // [4][128][33] = 67584 B
        float* xs  = (float*)(smem + 67584);        // [131][33]    = 17292 B
        float* b2s = (float*)(smem + 67584 + 17292 + 4);  // [128]
        const int b  = bm >> 12;
        const int t0 = bm & (T_LEN - 1);
        const int d0 = bn >> 2;
        for (int idx = tid; idx < 131 * 32; idx += 256) {
            int r = idx >> 5, c = idx & 31;
            int t = t0 - 3 + r;
            float v = 0.f;
            if (t >= 0) v = xin[((size_t)b * T_LEN + t) * D_HID + d0 + c];
            xs[r * 33 + c] = v;
        }
        if (tid < 128) b2s[tid] = b2[bn + tid];
        __syncthreads();
        #pragma unroll
        for (int mt = 0; mt < 4; mt++) {
            #pragma unroll
            for (int nt = 0; nt < 4; nt++) {
                int r0   = wm * 64 + mt * 16 + (l >> 2);
                int col0 = wn * 32 + nt * 8 + (l & 3) * 2;
                #pragma unroll
                for (int cc = 0; cc < 4; cc++) {
                    int r   = r0 + ((cc >> 1) << 3);
                    int col = col0 + (cc & 1);
                    float val = acc[mt][nt][cc] + b2s[col];
                    ksm[(((col & 3) * 128) + r) * 33 + (col >> 2)] = val;
                }
            }
        }
        __syncthreads();
        {
            int c = tid & 31, rg = tid >> 5;
            #pragma unroll
            for (int i = 0; i < 16; i++) {
                int r = rg * 16 + i;
                float y = 0.f;
                #pragma unroll
                for (int w = 0; w < 4; w++)
                    y += xs[(r + w) * 33 + c] * ksm[((w * 128) + r) * 33 + c];
                out[(size_t)(bm + r) * D_HID + d0 + c] = silu_f(y);
            }
        }
    }
}

// ---------------- launch ----------------------------------------------------
extern "C" void kernel_launch(void* const* d_in, const int* in_sizes, int n_in,
                              void* d_out, int out_size) {
    const float* x  = (const float*)d_in[0];   // [2,4096,2048]
    const float* w1 = (const float*)d_in[1];   // [2048,2048]
    const float* w2 = (const float*)d_in[2];   // [8192,2048]
    const float* b2 = (const float*)d_in[3];   // [8192]
    float* out = (float*)d_out;

    cudaFuncSetAttribute(gemm1p_kernel<0>, cudaFuncAttributeMaxDynamicSharedMemorySize, SMEM_BYTES);
    cudaFuncSetAttribute(gemm1p_kernel<1>, cudaFuncAttributeMaxDynamicSharedMemorySize, SMEM_BYTES);

    void *pxh, *pw1, *pw2;
    cudaGetSymbolAddress(&pxh, g_xh);
    cudaGetSymbolAddress(&pw1, g_w1h);
    cudaGetSymbolAddress(&pw2, g_w2h);

    {
        int ntot = NX4 + NW14 + NW24;
        round3_kernel<<<(ntot + 255) / 256, 256>>>(
            x, w1, w2, (__half*)pxh, (__half*)pw1, (__half*)pw2);
    }

    dim3 g1(D_HID / 128, M_ROWS / 128);   // (16, 64)
    gemm1p_kernel<0><<<g1, 256, SMEM_BYTES>>>(x, b2, out);

    dim3 g2(KW / 128, M_ROWS / 128);      // (64, 64)
    gemm1p_kernel<1><<<g2, 256, SMEM_BYTES>>>(x, b2, out);
}